// round 4
// baseline (speedup 1.0000x reference)
#include <cuda_runtime.h>
#include <cuda_bf16.h>
#include <math.h>

#define Tt 1024
#define Bb 16
#define Dd 1024
#define NB 64
#define BD (Bb*Dd)
#define OUT_OFS (Tt*Bb*Dd)

__device__ __align__(16) float g_pre[Tt*Bb*Dd];
__device__ __align__(16) __nv_bfloat16 g_hA[2][64*32*16]; // [phase][(kt*32+lt)*16 + rg*2+c]: 8 hi | 8 lo
__device__ __align__(16) __nv_bfloat16 g_xh[Tt*Bb*Dd], g_xl[Tt*Bb*Dd];
__device__ __align__(16) __nv_bfloat16 g_wh[Dd*Dd], g_wl[Dd*Dd];
__device__ __align__(16) float g_part[NB][Dd];
__device__ __align__(16) float g_vraw[Dd];
__device__ __align__(16) float g_uraw[Dd];
__device__ float g_ss[NB], g_ssu[NB];
__device__ unsigned g_arrive;
__device__ unsigned g_flag[NB];

__device__ __forceinline__ void mma16816(float* c, const unsigned* a, const unsigned* b) {
    asm volatile(
        "mma.sync.aligned.m16n8k16.row.col.f32.bf16.bf16.f32 "
        "{%0,%1,%2,%3},{%4,%5,%6,%7},{%8,%9},{%0,%1,%2,%3};\n"
        : "+f"(c[0]), "+f"(c[1]), "+f"(c[2]), "+f"(c[3])
        : "r"(a[0]), "r"(a[1]), "r"(a[2]), "r"(a[3]), "r"(b[0]), "r"(b[1]));
}

__device__ __forceinline__ void gbar(unsigned* nbar) {
    (*nbar)++;
    __syncthreads();
    if (threadIdx.x == 0) {
        __threadfence();
        atomicAdd(&g_arrive, 1u);
        unsigned tgt = (*nbar) * NB;
        while (*(volatile unsigned*)&g_arrive < tgt) { }
        __threadfence();
    }
    __syncthreads();
}

__device__ __forceinline__ int frag_idx(int b, int j) {
    int kt = j >> 4, c = j & 15;
    int lt = ((b & 7) << 2) | ((c >> 1) & 3);
    int rg = (b >> 3) | ((c >> 3) << 1);
    return (kt * 32 + lt) * 16 + rg * 2 + (c & 1);
}

// ---- init ----
__global__ void k_init(const float* __restrict__ h0, float* __restrict__ hall) {
    int e = blockIdx.x * 256 + threadIdx.x;
    if (e == 0) g_arrive = 0u;
    if (e < NB) g_flag[e] = 0u;
    int b = e >> 10, j = e & 1023;
    float v = h0[e];
    hall[e] = v;
    __nv_bfloat16 hb = __float2bfloat16(v);
    float rem = v - __bfloat162float(hb);
    __nv_bfloat16 lb = __float2bfloat16(rem);
    int fi = frag_idx(b, j);
    g_hA[0][fi] = hb;
    g_hA[0][fi + 8] = lb;
}

// ---- split fp32 -> bf16 hi/lo ----
__global__ void k_split(const float* __restrict__ src, __nv_bfloat16* __restrict__ hi,
                        __nv_bfloat16* __restrict__ lo, int n4) {
    int i = blockIdx.x * 256 + threadIdx.x;
    if (i >= n4) return;
    float4 v = ((const float4*)src)[i];
    __nv_bfloat162 a = __floats2bfloat162_rn(v.x, v.y);
    __nv_bfloat162 b = __floats2bfloat162_rn(v.z, v.w);
    float rx = v.x - __bfloat162float(a.x), ry = v.y - __bfloat162float(a.y);
    float rz = v.z - __bfloat162float(b.x), rw = v.w - __bfloat162float(b.y);
    __nv_bfloat162 c = __floats2bfloat162_rn(rx, ry);
    __nv_bfloat162 d = __floats2bfloat162_rn(rz, rw);
    uint2 sh = make_uint2(*(unsigned*)&a, *(unsigned*)&b);
    uint2 sl = make_uint2(*(unsigned*)&c, *(unsigned*)&d);
    ((uint2*)hi)[i] = sh;
    ((uint2*)lo)[i] = sl;
}

// ---- MMA GEMM: g_pre[m,n] = x[m,:].Wx[n,:] + b[n], 64(M)x128(N) tiles ----
__global__ void __launch_bounds__(256) k_gemm_mma(const __nv_bfloat16* __restrict__ Ah,
                                                  const __nv_bfloat16* __restrict__ Al,
                                                  const __nv_bfloat16* __restrict__ Bh,
                                                  const __nv_bfloat16* __restrict__ Bl,
                                                  const float* __restrict__ bias) {
    __shared__ __align__(16) __nv_bfloat16 sAh[2][64*24], sAl[2][64*24];
    __shared__ __align__(16) __nv_bfloat16 sBh[2][128*24], sBl[2][128*24];
    int tid = threadIdx.x, lane = tid & 31, w = tid >> 5;
    int mw = w >> 2, nw = w & 3;
    int m0 = blockIdx.y << 6, n0 = blockIdx.x << 7;
    int row2 = tid >> 1, hf = tid & 1;

    // stage 0
    {
        if (tid < 128) {
            uint4 va = *(const uint4*)(Ah + (size_t)(m0+row2)*Dd + hf*8);
            uint4 vb = *(const uint4*)(Al + (size_t)(m0+row2)*Dd + hf*8);
            *(uint4*)&sAh[0][row2*24 + hf*8] = va;
            *(uint4*)&sAl[0][row2*24 + hf*8] = vb;
        }
        uint4 vc = *(const uint4*)(Bh + (size_t)(n0+row2)*Dd + hf*8);
        uint4 vd = *(const uint4*)(Bl + (size_t)(n0+row2)*Dd + hf*8);
        *(uint4*)&sBh[0][row2*24 + hf*8] = vc;
        *(uint4*)&sBl[0][row2*24 + hf*8] = vd;
    }
    __syncthreads();

    float C[2][4][4];
#pragma unroll
    for (int mt = 0; mt < 2; mt++)
#pragma unroll
        for (int nt = 0; nt < 4; nt++)
#pragma unroll
            for (int r = 0; r < 4; r++) C[mt][nt][r] = 0.f;

    for (int kt = 0; kt < 64; kt++) {
        int cur = kt & 1;
        uint4 pa, pal, pb, pbl;
        if (kt < 63) {
            int k0 = (kt + 1) * 16;
            if (tid < 128) {
                pa  = *(const uint4*)(Ah + (size_t)(m0+row2)*Dd + k0 + hf*8);
                pal = *(const uint4*)(Al + (size_t)(m0+row2)*Dd + k0 + hf*8);
            }
            pb  = *(const uint4*)(Bh + (size_t)(n0+row2)*Dd + k0 + hf*8);
            pbl = *(const uint4*)(Bl + (size_t)(n0+row2)*Dd + k0 + hf*8);
        }
        unsigned ah[2][4], al[2][4], bh[4][2], bl[4][2];
#pragma unroll
        for (int mt = 0; mt < 2; mt++)
#pragma unroll
            for (int r = 0; r < 4; r++) {
                int rr = mw*32 + mt*16 + ((r & 1) << 3) + (lane >> 2);
                int cc = ((lane & 3) << 1) + ((r >> 1) << 3);
                ah[mt][r] = *(const unsigned*)&sAh[cur][rr*24 + cc];
                al[mt][r] = *(const unsigned*)&sAl[cur][rr*24 + cc];
            }
#pragma unroll
        for (int nt = 0; nt < 4; nt++)
#pragma unroll
            for (int r = 0; r < 2; r++) {
                int nn = nw*32 + nt*8 + (lane >> 2);
                int kk = ((lane & 3) << 1) + (r << 3);
                bh[nt][r] = *(const unsigned*)&sBh[cur][nn*24 + kk];
                bl[nt][r] = *(const unsigned*)&sBl[cur][nn*24 + kk];
            }
#pragma unroll
        for (int mt = 0; mt < 2; mt++)
#pragma unroll
            for (int nt = 0; nt < 4; nt++) {
                mma16816(C[mt][nt], ah[mt], bh[nt]);
                mma16816(C[mt][nt], al[mt], bh[nt]);
                mma16816(C[mt][nt], ah[mt], bl[nt]);
            }
        if (kt < 63) {
            int nb = cur ^ 1;
            __syncthreads();
            if (tid < 128) {
                *(uint4*)&sAh[nb][row2*24 + hf*8] = pa;
                *(uint4*)&sAl[nb][row2*24 + hf*8] = pal;
            }
            *(uint4*)&sBh[nb][row2*24 + hf*8] = pb;
            *(uint4*)&sBl[nb][row2*24 + hf*8] = pbl;
            __syncthreads();
        }
    }
#pragma unroll
    for (int mt = 0; mt < 2; mt++)
#pragma unroll
        for (int nt = 0; nt < 4; nt++) {
            int rr = m0 + mw*32 + mt*16 + (lane >> 2);
            int cc = n0 + nw*32 + nt*8 + ((lane & 3) << 1);
            float b0 = bias[cc], b1 = bias[cc+1];
            float2 v0 = make_float2(C[mt][nt][0] + b0, C[mt][nt][1] + b1);
            float2 v1 = make_float2(C[mt][nt][2] + b0, C[mt][nt][3] + b1);
            *(float2*)&g_pre[(size_t)rr*Dd + cc] = v0;
            *(float2*)&g_pre[(size_t)(rr+8)*Dd + cc] = v1;
        }
}

// ---- persistent: power iteration + mma recurrence, flag-based sync ----
__global__ void __launch_bounds__(256) k_recur(const float* __restrict__ Wh,
                                               const float* __restrict__ lr,
                                               const float* __restrict__ u0,
                                               const float* __restrict__ z,
                                               float* __restrict__ outp,
                                               float* __restrict__ hall) {
    __shared__ float sred[8 * 256];
    __shared__ __align__(16) __nv_bfloat16 sstage[512];
    __shared__ float s_u[16];
    int tid = threadIdx.x, w = tid >> 5, lane = tid & 31, blk = blockIdx.x;
    unsigned nbar = 0;

    // ===== power iteration (3 iters) =====
    float invu = 1.f, ssu = 0.f;
    for (int it = 0; it < 3; it++) {
        if (tid < 16) {
            float uu = (it == 0) ? u0[blk*16 + tid] : __ldcg(&g_uraw[blk*16 + tid]) * invu;
            s_u[tid] = uu;
        }
        __syncthreads();
        {
            float4 acc = make_float4(0.f, 0.f, 0.f, 0.f);
            const float* wp = Wh + (size_t)(blk*16) * Dd + tid*4;
#pragma unroll
            for (int r = 0; r < 16; r++) {
                float uu = s_u[r];
                float4 wv = *(const float4*)(wp + (size_t)r * Dd);
                acc.x += uu*wv.x; acc.y += uu*wv.y; acc.z += uu*wv.z; acc.w += uu*wv.w;
            }
            *(float4*)&g_part[blk][tid*4] = acc;
        }
        gbar(&nbar);
        {
            int c = blk*16 + (tid & 15);
            int p0 = tid >> 4;
            float v = 0.f;
#pragma unroll
            for (int q = 0; q < 4; q++) v += __ldcg(&g_part[p0 + q*16][c]);
            sred[p0 * 16 + (tid & 15)] = v;
            __syncthreads();
            if (tid < 16) {
                float s = 0.f;
#pragma unroll
                for (int p = 0; p < 16; p++) s += sred[p*16 + tid];
                g_vraw[blk*16 + tid] = s;
                float ss = s * s;
#pragma unroll
                for (int o = 8; o > 0; o >>= 1) ss += __shfl_xor_sync(0xffffu, ss, o);
                if (tid == 0) g_ss[blk] = ss;
            }
        }
        gbar(&nbar);
        float ssv = 0.f;
#pragma unroll
        for (int q = 0; q < NB; q++) ssv += __ldcg(&g_ss[q]);
        float invv = 1.f / (sqrtf(ssv) + 1e-8f);
        __syncthreads();
        {
            float* sv = sred;
            for (int q = tid; q < Dd; q += 256) sv[q] = __ldcg(&g_vraw[q]) * invv;
            __syncthreads();
            float ro[2];
#pragma unroll
            for (int rr = 0; rr < 2; rr++) {
                int row = blk*16 + w*2 + rr;
                const float4* wp = (const float4*)(Wh + (size_t)row * Dd);
                float acc = 0.f;
#pragma unroll
                for (int q = 0; q < 8; q++) {
                    float4 a = wp[q*32 + lane];
                    float4 b = *(const float4*)&sv[(q*32 + lane)*4];
                    acc += a.x*b.x + a.y*b.y + a.z*b.z + a.w*b.w;
                }
#pragma unroll
                for (int o = 16; o > 0; o >>= 1) acc += __shfl_xor_sync(0xffffffffu, acc, o);
                ro[rr] = acc;
                if (lane == 0) g_uraw[row] = acc;
            }
            __syncthreads();
            if (lane == 0) { sred[w*2] = ro[0]; sred[w*2+1] = ro[1]; }
            __syncthreads();
            if (tid < 16) {
                float x = sred[tid];
                float ss = x * x;
#pragma unroll
                for (int o = 8; o > 0; o >>= 1) ss += __shfl_xor_sync(0xffffu, ss, o);
                if (tid == 0) g_ssu[blk] = ss;
            }
        }
        gbar(&nbar);
        ssu = 0.f;
#pragma unroll
        for (int q = 0; q < NB; q++) ssu += __ldcg(&g_ssu[q]);
        invu = 1.f / (sqrtf(ssu) + 1e-8f);
        __syncthreads();
    }
    float sigma = ssu / (sqrtf(ssu) + 1e-8f);

    // ===== build W_h_eff fragments =====
    int i0 = blk * 16;
    float scl[2];
#pragma unroll
    for (int nt = 0; nt < 2; nt++) {
        int d = i0 + nt*8 + (lane >> 2);
        float rad = 0.999f / (1.f + expf(-lr[d]));
        scl[nt] = rad / (sigma + 1e-8f);
    }
    unsigned WHI[8][2][2], WLO[8][2][2];
#pragma unroll
    for (int k8 = 0; k8 < 8; k8++)
#pragma unroll
        for (int nt = 0; nt < 2; nt++)
#pragma unroll
            for (int r = 0; r < 2; r++) {
                int d = i0 + nt*8 + (lane >> 2);
                int jb = (w*8 + k8)*16 + ((lane & 3) << 1) + r*8;
                float v0 = Wh[(size_t)d * Dd + jb]     * scl[nt];
                float v1 = Wh[(size_t)d * Dd + jb + 1] * scl[nt];
                __nv_bfloat162 hh = __floats2bfloat162_rn(v0, v1);
                float r0 = v0 - __bfloat162float(hh.x);
                float r1 = v1 - __bfloat162float(hh.y);
                __nv_bfloat162 ll = __floats2bfloat162_rn(r0, r1);
                WHI[k8][nt][r] = *(unsigned*)&hh;
                WLO[k8][nt][r] = *(unsigned*)&ll;
            }

    // ===== recurrence =====
    int gb = tid >> 4, dl = tid & 15, gd = i0 + dl;
    int lt_s = ((gb & 7) << 2) | ((dl >> 1) & 3);
    int rg_s = (gb >> 3) | ((dl >> 3) << 1);
    int li = lt_s * 16 + rg_s * 2 + (dl & 1);

    for (int t = 0; t < Tt; t++) {
        size_t row = ((size_t)(t*Bb) + gb) * Dd + gd;
        float pre_v = __ldcs(&g_pre[row]);
        float z_v   = __ldcs(&z[row]);

        if (t > 0) {
            if (lane < 8) {
                const unsigned* fp = &g_flag[w*8 + lane];
                unsigned f;
                do {
                    asm volatile("ld.acquire.gpu.global.u32 %0, [%1];" : "=r"(f) : "l"(fp) : "memory");
                } while (f < (unsigned)t);
            }
            __syncwarp();
        }

        const uint4* src = (const uint4*)g_hA[t & 1];
        float Ca0[4]={0,0,0,0}, Cb0[4]={0,0,0,0}, Ca1[4]={0,0,0,0}, Cb1[4]={0,0,0,0};
        uint4 bh[4], bl[4];
#pragma unroll
        for (int p = 0; p < 4; p++) {
            int kt = w*8 + p;
            bh[p] = __ldcg(src + (kt*32 + lane)*2);
            bl[p] = __ldcg(src + (kt*32 + lane)*2 + 1);
        }
#pragma unroll
        for (int k8 = 0; k8 < 8; k8++) {
            unsigned ah[4] = {bh[k8 & 3].x, bh[k8 & 3].y, bh[k8 & 3].z, bh[k8 & 3].w};
            unsigned al[4] = {bl[k8 & 3].x, bl[k8 & 3].y, bl[k8 & 3].z, bl[k8 & 3].w};
            if (k8 < 4) {
                int kt = w*8 + k8 + 4;
                bh[k8] = __ldcg(src + (kt*32 + lane)*2);
                bl[k8] = __ldcg(src + (kt*32 + lane)*2 + 1);
            }
            mma16816(Ca0, ah, WHI[k8][0]);
            mma16816(Cb0, al, WHI[k8][0]);
            mma16816(Cb0, ah, WLO[k8][0]);
            mma16816(Ca1, ah, WHI[k8][1]);
            mma16816(Cb1, al, WHI[k8][1]);
            mma16816(Cb1, ah, WLO[k8][1]);
        }
        {
            int r = lane >> 2, c2 = (lane & 3) << 1;
            float* dst = &sred[w * 256];
            dst[ r*16      + c2    ] = Ca0[0] + Cb0[0];
            dst[ r*16      + c2 + 1] = Ca0[1] + Cb0[1];
            dst[(r+8)*16   + c2    ] = Ca0[2] + Cb0[2];
            dst[(r+8)*16   + c2 + 1] = Ca0[3] + Cb0[3];
            dst[ r*16  + 8 + c2    ] = Ca1[0] + Cb1[0];
            dst[ r*16  + 8 + c2 + 1] = Ca1[1] + Cb1[1];
            dst[(r+8)*16+8 + c2    ] = Ca1[2] + Cb1[2];
            dst[(r+8)*16+8 + c2 + 1] = Ca1[3] + Cb1[3];
        }
        __syncthreads();
        float acc = pre_v;
#pragma unroll
        for (int ww = 0; ww < 8; ww++) acc += sred[ww*256 + tid];
        float h = tanhf(acc);
        float gate = z_v / (1.f + expf(-z_v));
        __nv_bfloat16 hb = __float2bfloat16(h);
        float rem = h - __bfloat162float(hb);
        __nv_bfloat16 lb = __float2bfloat16(rem);
        sstage[li] = hb;
        sstage[li + 8] = lb;
        __syncthreads();
        if (w == 0) {
            uint4* dst = (uint4*)(g_hA[(t+1) & 1]) + blk*64;
            const uint4* s4 = (const uint4*)sstage;
            __stcg(dst + lane, s4[lane]);
            __stcg(dst + 32 + lane, s4[32 + lane]);
            __syncwarp();
            if (lane == 0)
                asm volatile("st.release.gpu.global.u32 [%0], %1;" :: "l"(&g_flag[blk]), "r"((unsigned)(t+1)) : "memory");
        }
        outp[row] = h * gate;
        hall[(size_t)(t+1) * BD + gb*Dd + gd] = h;
    }
}

extern "C" void kernel_launch(void* const* d_in, const int* in_sizes, int n_in,
                              void* d_out, int out_size) {
    const float* x  = (const float*)d_in[0];
    const float* z  = (const float*)d_in[1];
    const float* h0 = (const float*)d_in[2];
    const float* Wx = (const float*)d_in[3];
    const float* Wh = (const float*)d_in[4];
    const float* lr = (const float*)d_in[5];
    const float* b  = (const float*)d_in[6];
    const float* u0 = (const float*)d_in[7];
    float* outp = (float*)d_out;
    float* hall = (float*)d_out + OUT_OFS;

    k_init<<<64, 256>>>(h0, hall);
    k_split<<<(Tt*Bb*Dd/4 + 255)/256, 256>>>(x, g_xh, g_xl, Tt*Bb*Dd/4);
    k_split<<<(Dd*Dd/4 + 255)/256, 256>>>(Wx, g_wh, g_wl, Dd*Dd/4);
    dim3 gg(Dd/128, (Tt*Bb)/64);
    k_gemm_mma<<<gg, 256>>>(g_xh, g_xl, g_wh, g_wl, b);
    k_recur<<<NB, 256>>>(Wh, lr, u0, z, outp, hall);
}

// round 5
// speedup vs baseline: 1.0474x; 1.0474x over previous
#include <cuda_runtime.h>
#include <cuda_bf16.h>
#include <math.h>

#define Tt 1024
#define Bb 16
#define Dd 1024
#define NB 64
#define BD (Bb*Dd)
#define OUT_OFS (Tt*Bb*Dd)

__device__ __align__(16) float g_pre[Tt*Bb*Dd];
__device__ __align__(16) __nv_bfloat16 g_hA[2][64*32*16]; // [phase][(kt*32+lt)*16 + rg*2+c]: 8 hi | 8 lo
__device__ __align__(16) __nv_bfloat16 g_xh[Tt*Bb*Dd], g_xl[Tt*Bb*Dd];
__device__ __align__(16) __nv_bfloat16 g_wh[Dd*Dd], g_wl[Dd*Dd];
__device__ __align__(16) float g_part[NB][Dd];
__device__ __align__(16) float g_vraw[Dd];
__device__ __align__(16) float g_uraw[Dd];
__device__ float g_ss[NB], g_ssu[NB];
__device__ unsigned g_arrive;

__device__ __forceinline__ void mma16816(float* c, const unsigned* a, const unsigned* b) {
    asm volatile(
        "mma.sync.aligned.m16n8k16.row.col.f32.bf16.bf16.f32 "
        "{%0,%1,%2,%3},{%4,%5,%6,%7},{%8,%9},{%0,%1,%2,%3};\n"
        : "+f"(c[0]), "+f"(c[1]), "+f"(c[2]), "+f"(c[3])
        : "r"(a[0]), "r"(a[1]), "r"(a[2]), "r"(a[3]), "r"(b[0]), "r"(b[1]));
}

__device__ __forceinline__ void gbar(unsigned* nbar) {
    (*nbar)++;
    __syncthreads();
    if (threadIdx.x == 0) {
        __threadfence();
        atomicAdd(&g_arrive, 1u);
        unsigned tgt = (*nbar) * NB;
        while (*(volatile unsigned*)&g_arrive < tgt) { }
        __threadfence();
    }
    __syncthreads();
}

__device__ __forceinline__ int frag_idx(int b, int j) {
    int kt = j >> 4, c = j & 15;
    int lt = ((b & 7) << 2) | ((c >> 1) & 3);
    int rg = (b >> 3) | ((c >> 3) << 1);
    return (kt * 32 + lt) * 16 + rg * 2 + (c & 1);
}

// ---- init ----
__global__ void k_init(const float* __restrict__ h0, float* __restrict__ hall) {
    int e = blockIdx.x * 256 + threadIdx.x;
    if (e == 0) g_arrive = 0u;
    int b = e >> 10, j = e & 1023;
    float v = h0[e];
    hall[e] = v;
    __nv_bfloat16 hb = __float2bfloat16(v);
    float rem = v - __bfloat162float(hb);
    __nv_bfloat16 lb = __float2bfloat16(rem);
    int fi = frag_idx(b, j);
    g_hA[0][fi] = hb;
    g_hA[0][fi + 8] = lb;
}

// ---- split fp32 -> bf16 hi/lo ----
__global__ void k_split(const float* __restrict__ src, __nv_bfloat16* __restrict__ hi,
                        __nv_bfloat16* __restrict__ lo, int n4) {
    int i = blockIdx.x * 256 + threadIdx.x;
    if (i >= n4) return;
    float4 v = ((const float4*)src)[i];
    __nv_bfloat162 a = __floats2bfloat162_rn(v.x, v.y);
    __nv_bfloat162 b = __floats2bfloat162_rn(v.z, v.w);
    float rx = v.x - __bfloat162float(a.x), ry = v.y - __bfloat162float(a.y);
    float rz = v.z - __bfloat162float(b.x), rw = v.w - __bfloat162float(b.y);
    __nv_bfloat162 c = __floats2bfloat162_rn(rx, ry);
    __nv_bfloat162 d = __floats2bfloat162_rn(rz, rw);
    uint2 sh = make_uint2(*(unsigned*)&a, *(unsigned*)&b);
    uint2 sl = make_uint2(*(unsigned*)&c, *(unsigned*)&d);
    ((uint2*)hi)[i] = sh;
    ((uint2*)lo)[i] = sl;
}

// ---- MMA GEMM: g_pre[m,n] = x[m,:].Wx[n,:] + b[n], 64(M)x128(N) tiles ----
__global__ void __launch_bounds__(256) k_gemm_mma(const __nv_bfloat16* __restrict__ Ah,
                                                  const __nv_bfloat16* __restrict__ Al,
                                                  const __nv_bfloat16* __restrict__ Bh,
                                                  const __nv_bfloat16* __restrict__ Bl,
                                                  const float* __restrict__ bias) {
    __shared__ __align__(16) __nv_bfloat16 sAh[2][64*24], sAl[2][64*24];
    __shared__ __align__(16) __nv_bfloat16 sBh[2][128*24], sBl[2][128*24];
    int tid = threadIdx.x, lane = tid & 31, w = tid >> 5;
    int mw = w >> 2, nw = w & 3;
    int m0 = blockIdx.y << 6, n0 = blockIdx.x << 7;
    int row2 = tid >> 1, hf = tid & 1;

    {
        if (tid < 128) {
            uint4 va = *(const uint4*)(Ah + (size_t)(m0+row2)*Dd + hf*8);
            uint4 vb = *(const uint4*)(Al + (size_t)(m0+row2)*Dd + hf*8);
            *(uint4*)&sAh[0][row2*24 + hf*8] = va;
            *(uint4*)&sAl[0][row2*24 + hf*8] = vb;
        }
        uint4 vc = *(const uint4*)(Bh + (size_t)(n0+row2)*Dd + hf*8);
        uint4 vd = *(const uint4*)(Bl + (size_t)(n0+row2)*Dd + hf*8);
        *(uint4*)&sBh[0][row2*24 + hf*8] = vc;
        *(uint4*)&sBl[0][row2*24 + hf*8] = vd;
    }
    __syncthreads();

    float C[2][4][4];
#pragma unroll
    for (int mt = 0; mt < 2; mt++)
#pragma unroll
        for (int nt = 0; nt < 4; nt++)
#pragma unroll
            for (int r = 0; r < 4; r++) C[mt][nt][r] = 0.f;

    for (int kt = 0; kt < 64; kt++) {
        int cur = kt & 1;
        uint4 pa, pal, pb, pbl;
        if (kt < 63) {
            int k0 = (kt + 1) * 16;
            if (tid < 128) {
                pa  = *(const uint4*)(Ah + (size_t)(m0+row2)*Dd + k0 + hf*8);
                pal = *(const uint4*)(Al + (size_t)(m0+row2)*Dd + k0 + hf*8);
            }
            pb  = *(const uint4*)(Bh + (size_t)(n0+row2)*Dd + k0 + hf*8);
            pbl = *(const uint4*)(Bl + (size_t)(n0+row2)*Dd + k0 + hf*8);
        }
        unsigned ah[2][4], al[2][4], bh[4][2], bl[4][2];
#pragma unroll
        for (int mt = 0; mt < 2; mt++)
#pragma unroll
            for (int r = 0; r < 4; r++) {
                int rr = mw*32 + mt*16 + ((r & 1) << 3) + (lane >> 2);
                int cc = ((lane & 3) << 1) + ((r >> 1) << 3);
                ah[mt][r] = *(const unsigned*)&sAh[cur][rr*24 + cc];
                al[mt][r] = *(const unsigned*)&sAl[cur][rr*24 + cc];
            }
#pragma unroll
        for (int nt = 0; nt < 4; nt++)
#pragma unroll
            for (int r = 0; r < 2; r++) {
                int nn = nw*32 + nt*8 + (lane >> 2);
                int kk = ((lane & 3) << 1) + (r << 3);
                bh[nt][r] = *(const unsigned*)&sBh[cur][nn*24 + kk];
                bl[nt][r] = *(const unsigned*)&sBl[cur][nn*24 + kk];
            }
#pragma unroll
        for (int mt = 0; mt < 2; mt++)
#pragma unroll
            for (int nt = 0; nt < 4; nt++) {
                mma16816(C[mt][nt], ah[mt], bh[nt]);
                mma16816(C[mt][nt], al[mt], bh[nt]);
                mma16816(C[mt][nt], ah[mt], bl[nt]);
            }
        if (kt < 63) {
            int nb = cur ^ 1;
            __syncthreads();
            if (tid < 128) {
                *(uint4*)&sAh[nb][row2*24 + hf*8] = pa;
                *(uint4*)&sAl[nb][row2*24 + hf*8] = pal;
            }
            *(uint4*)&sBh[nb][row2*24 + hf*8] = pb;
            *(uint4*)&sBl[nb][row2*24 + hf*8] = pbl;
            __syncthreads();
        }
    }
#pragma unroll
    for (int mt = 0; mt < 2; mt++)
#pragma unroll
        for (int nt = 0; nt < 4; nt++) {
            int rr = m0 + mw*32 + mt*16 + (lane >> 2);
            int cc = n0 + nw*32 + nt*8 + ((lane & 3) << 1);
            float b0 = bias[cc], b1 = bias[cc+1];
            float2 v0 = make_float2(C[mt][nt][0] + b0, C[mt][nt][1] + b1);
            float2 v1 = make_float2(C[mt][nt][2] + b0, C[mt][nt][3] + b1);
            *(float2*)&g_pre[(size_t)rr*Dd + cc] = v0;
            *(float2*)&g_pre[(size_t)(rr+8)*Dd + cc] = v1;
        }
}

// ---- persistent: power iteration prologue + mma recurrence. 64 blocks x 256 ----
__global__ void __launch_bounds__(256) k_recur(const float* __restrict__ Wh,
                                               const float* __restrict__ lr,
                                               const float* __restrict__ u0,
                                               const float* __restrict__ z,
                                               float* __restrict__ outp,
                                               float* __restrict__ hall) {
    __shared__ float sred[8 * 256];
    __shared__ float s_u[16];
    int tid = threadIdx.x, w = tid >> 5, lane = tid & 31, blk = blockIdx.x;
    unsigned nbar = 0;

    // ===== power iteration (3 iters) =====
    float invu = 1.f, ssu = 0.f;
    for (int it = 0; it < 3; it++) {
        if (tid < 16) {
            float uu = (it == 0) ? u0[blk*16 + tid] : __ldcg(&g_uraw[blk*16 + tid]) * invu;
            s_u[tid] = uu;
        }
        __syncthreads();
        {
            float4 acc = make_float4(0.f, 0.f, 0.f, 0.f);
            const float* wp = Wh + (size_t)(blk*16) * Dd + tid*4;
#pragma unroll
            for (int r = 0; r < 16; r++) {
                float uu = s_u[r];
                float4 wv = *(const float4*)(wp + (size_t)r * Dd);
                acc.x += uu*wv.x; acc.y += uu*wv.y; acc.z += uu*wv.z; acc.w += uu*wv.w;
            }
            *(float4*)&g_part[blk][tid*4] = acc;
        }
        gbar(&nbar);
        {
            int c = blk*16 + (tid & 15);
            int p0 = tid >> 4;
            float v = 0.f;
#pragma unroll
            for (int q = 0; q < 4; q++) v += __ldcg(&g_part[p0 + q*16][c]);
            sred[p0 * 16 + (tid & 15)] = v;
            __syncthreads();
            if (tid < 16) {
                float s = 0.f;
#pragma unroll
                for (int p = 0; p < 16; p++) s += sred[p*16 + tid];
                g_vraw[blk*16 + tid] = s;
                float ss = s * s;
#pragma unroll
                for (int o = 8; o > 0; o >>= 1) ss += __shfl_xor_sync(0xffffu, ss, o);
                if (tid == 0) g_ss[blk] = ss;
            }
        }
        gbar(&nbar);
        float ssv = 0.f;
#pragma unroll
        for (int q = 0; q < NB; q++) ssv += __ldcg(&g_ss[q]);
        float invv = 1.f / (sqrtf(ssv) + 1e-8f);
        __syncthreads();
        {
            float* sv = sred;
            for (int q = tid; q < Dd; q += 256) sv[q] = __ldcg(&g_vraw[q]) * invv;
            __syncthreads();
            float ro[2];
#pragma unroll
            for (int rr = 0; rr < 2; rr++) {
                int row = blk*16 + w*2 + rr;
                const float4* wp = (const float4*)(Wh + (size_t)row * Dd);
                float acc = 0.f;
#pragma unroll
                for (int q = 0; q < 8; q++) {
                    float4 a = wp[q*32 + lane];
                    float4 b = *(const float4*)&sv[(q*32 + lane)*4];
                    acc += a.x*b.x + a.y*b.y + a.z*b.z + a.w*b.w;
                }
#pragma unroll
                for (int o = 16; o > 0; o >>= 1) acc += __shfl_xor_sync(0xffffffffu, acc, o);
                ro[rr] = acc;
                if (lane == 0) g_uraw[row] = acc;
            }
            __syncthreads();
            if (lane == 0) { sred[w*2] = ro[0]; sred[w*2+1] = ro[1]; }
            __syncthreads();
            if (tid < 16) {
                float x = sred[tid];
                float ss = x * x;
#pragma unroll
                for (int o = 8; o > 0; o >>= 1) ss += __shfl_xor_sync(0xffffu, ss, o);
                if (tid == 0) g_ssu[blk] = ss;
            }
        }
        gbar(&nbar);
        ssu = 0.f;
#pragma unroll
        for (int q = 0; q < NB; q++) ssu += __ldcg(&g_ssu[q]);
        invu = 1.f / (sqrtf(ssu) + 1e-8f);
        __syncthreads();
    }
    float sigma = ssu / (sqrtf(ssu) + 1e-8f);

    // ===== build W_h_eff fragments in registers =====
    int i0 = blk * 16;
    float scl[2];
#pragma unroll
    for (int nt = 0; nt < 2; nt++) {
        int d = i0 + nt*8 + (lane >> 2);
        float rad = 0.999f / (1.f + expf(-lr[d]));
        scl[nt] = rad / (sigma + 1e-8f);
    }
    unsigned WHI[8][2][2], WLO[8][2][2];
#pragma unroll
    for (int k8 = 0; k8 < 8; k8++)
#pragma unroll
        for (int nt = 0; nt < 2; nt++)
#pragma unroll
            for (int r = 0; r < 2; r++) {
                int d = i0 + nt*8 + (lane >> 2);
                int jb = (w*8 + k8)*16 + ((lane & 3) << 1) + r*8;
                float v0 = Wh[(size_t)d * Dd + jb]     * scl[nt];
                float v1 = Wh[(size_t)d * Dd + jb + 1] * scl[nt];
                __nv_bfloat162 hh = __floats2bfloat162_rn(v0, v1);
                float r0 = v0 - __bfloat162float(hh.x);
                float r1 = v1 - __bfloat162float(hh.y);
                __nv_bfloat162 ll = __floats2bfloat162_rn(r0, r1);
                WHI[k8][nt][r] = *(unsigned*)&hh;
                WLO[k8][nt][r] = *(unsigned*)&ll;
            }

    // ===== recurrence =====
    int gb = tid >> 4, dl = tid & 15, gd = i0 + dl;
    for (int t = 0; t < Tt; t++) {
        size_t row = ((size_t)(t*Bb) + gb) * Dd + gd;
        float pre_v = __ldcs(&g_pre[row]);
        float z_v   = __ldcs(&z[row]);

        const uint4* src = (const uint4*)g_hA[t & 1];
        float C0[4] = {0.f,0.f,0.f,0.f}, C1[4] = {0.f,0.f,0.f,0.f};
        uint4 bh[4], bl[4];
#pragma unroll
        for (int p = 0; p < 4; p++) {
            int kt = w*8 + p;
            bh[p] = __ldcg(src + (kt*32 + lane)*2);
            bl[p] = __ldcg(src + (kt*32 + lane)*2 + 1);
        }
#pragma unroll
        for (int k8 = 0; k8 < 8; k8++) {
            unsigned ah[4] = {bh[k8 & 3].x, bh[k8 & 3].y, bh[k8 & 3].z, bh[k8 & 3].w};
            unsigned al[4] = {bl[k8 & 3].x, bl[k8 & 3].y, bl[k8 & 3].z, bl[k8 & 3].w};
            if (k8 < 4) {
                int kt = w*8 + k8 + 4;
                bh[k8] = __ldcg(src + (kt*32 + lane)*2);
                bl[k8] = __ldcg(src + (kt*32 + lane)*2 + 1);
            }
            mma16816(C0, ah, WHI[k8][0]);
            mma16816(C0, al, WHI[k8][0]);
            mma16816(C0, ah, WLO[k8][0]);
            mma16816(C1, ah, WHI[k8][1]);
            mma16816(C1, al, WHI[k8][1]);
            mma16816(C1, ah, WLO[k8][1]);
        }
        {
            int r = lane >> 2, c2 = (lane & 3) << 1;
            float* dst = &sred[w * 256];
            dst[ r*16      + c2    ] = C0[0];
            dst[ r*16      + c2 + 1] = C0[1];
            dst[(r+8)*16   + c2    ] = C0[2];
            dst[(r+8)*16   + c2 + 1] = C0[3];
            dst[ r*16  + 8 + c2    ] = C1[0];
            dst[ r*16  + 8 + c2 + 1] = C1[1];
            dst[(r+8)*16+8 + c2    ] = C1[2];
            dst[(r+8)*16+8 + c2 + 1] = C1[3];
        }
        __syncthreads();
        float acc = pre_v;
#pragma unroll
        for (int ww = 0; ww < 8; ww++) acc += sred[ww*256 + tid];
        float h = tanhf(acc);
        float gate = z_v / (1.f + expf(-z_v));
        outp[row] = h * gate;
        hall[(size_t)(t+1) * BD + gb*Dd + gd] = h;
        __nv_bfloat16 hb = __float2bfloat16(h);
        float rem = h - __bfloat162float(hb);
        __nv_bfloat16 lb = __float2bfloat16(rem);
        int fi = frag_idx(gb, gd);
        __nv_bfloat16* df = &g_hA[(t+1) & 1][fi];
        df[0] = hb;
        df[8] = lb;
        gbar(&nbar);
    }
}

extern "C" void kernel_launch(void* const* d_in, const int* in_sizes, int n_in,
                              void* d_out, int out_size) {
    const float* x  = (const float*)d_in[0];
    const float* z  = (const float*)d_in[1];
    const float* h0 = (const float*)d_in[2];
    const float* Wx = (const float*)d_in[3];
    const float* Wh = (const float*)d_in[4];
    const float* lr = (const float*)d_in[5];
    const float* b  = (const float*)d_in[6];
    const float* u0 = (const float*)d_in[7];
    float* outp = (float*)d_out;
    float* hall = (float*)d_out + OUT_OFS;

    k_init<<<64, 256>>>(h0, hall);
    k_split<<<(Tt*Bb*Dd/4 + 255)/256, 256>>>(x, g_xh, g_xl, Tt*Bb*Dd/4);
    k_split<<<(Dd*Dd/4 + 255)/256, 256>>>(Wx, g_wh, g_wl, Dd*Dd/4);
    dim3 gg(Dd/128, (Tt*Bb)/64);
    k_gemm_mma<<<gg, 256>>>(g_xh, g_xl, g_wh, g_wl, b);
    k_recur<<<NB, 256>>>(Wh, lr, u0, z, outp, hall);
}

// round 6
// speedup vs baseline: 2.8514x; 2.7223x over previous
#include <cuda_runtime.h>
#include <cuda_bf16.h>
#include <math.h>

#define Tt 1024
#define Bb 16
#define Dd 1024
#define NB 64
#define BD (Bb*Dd)
#define OUT_OFS (Tt*Bb*Dd)

__device__ __align__(16) float g_pre[Tt*Bb*Dd];
__device__ __align__(16) __nv_bfloat16 g_hA[2][64*32*16]; // [phase][(kt*32+lt)*16 + rg*2+c]: 8 hi | 8 lo
__device__ __align__(16) float g_part[NB][Dd];
__device__ __align__(16) float g_vraw[Dd];
__device__ __align__(16) float g_uraw[Dd];
__device__ float g_ss[NB], g_ssu[NB];
__device__ unsigned g_arrive;
__device__ __align__(128) unsigned g_flag[NB];

__device__ __forceinline__ void mma16816(float* c, const unsigned* a, const unsigned* b) {
    asm volatile(
        "mma.sync.aligned.m16n8k16.row.col.f32.bf16.bf16.f32 "
        "{%0,%1,%2,%3},{%4,%5,%6,%7},{%8,%9},{%0,%1,%2,%3};\n"
        : "+f"(c[0]), "+f"(c[1]), "+f"(c[2]), "+f"(c[3])
        : "r"(a[0]), "r"(a[1]), "r"(a[2]), "r"(a[3]), "r"(b[0]), "r"(b[1]));
}

__device__ __forceinline__ void gbar(unsigned* nbar) {
    (*nbar)++;
    __syncthreads();
    if (threadIdx.x == 0) {
        __threadfence();
        atomicAdd(&g_arrive, 1u);
        unsigned tgt = (*nbar) * NB;
        while (*(volatile unsigned*)&g_arrive < tgt) { }
        __threadfence();
    }
    __syncthreads();
}

__device__ __forceinline__ int frag_idx(int b, int j) {
    int kt = j >> 4, c = j & 15;
    int lt = ((b & 7) << 2) | ((c >> 1) & 3);
    int rg = (b >> 3) | ((c >> 3) << 1);
    return (kt * 32 + lt) * 16 + rg * 2 + (c & 1);
}

// ---- init ----
__global__ void k_init(const float* __restrict__ h0, float* __restrict__ hall) {
    int e = blockIdx.x * 256 + threadIdx.x;
    if (e == 0) g_arrive = 0u;
    if (e < NB) g_flag[e] = 0u;
    int b = e >> 10, j = e & 1023;
    float v = h0[e];
    hall[e] = v;
    __nv_bfloat16 hb = __float2bfloat16(v);
    float rem = v - __bfloat162float(hb);
    __nv_bfloat16 lb = __float2bfloat16(rem);
    int fi = frag_idx(b, j);
    g_hA[0][fi] = hb;
    g_hA[0][fi + 8] = lb;
}

// ---- GEMM: g_pre[m,n] = x[m,:].Wx[n,:] + b[n]  (fp32 SIMT 128x128x8, proven) ----
__global__ void __launch_bounds__(256) k_gemm(const float* __restrict__ A,
                                              const float* __restrict__ Bw,
                                              const float* __restrict__ bias) {
    __shared__ float As[2][8][132], Bs[2][8][132];
    int tid = threadIdx.x;
    int m0 = blockIdx.y << 7, n0 = blockIdx.x << 7;
    int srow = tid >> 1, skq = (tid & 1) << 2;
    const float* ap = A  + (size_t)(m0 + srow) * Dd + skq;
    const float* bp = Bw + (size_t)(n0 + srow) * Dd + skq;
    int tx = tid & 15, ty = tid >> 4;

    float4 a4 = *(const float4*)ap;
    float4 b4 = *(const float4*)bp;
    As[0][skq+0][srow]=a4.x; As[0][skq+1][srow]=a4.y; As[0][skq+2][srow]=a4.z; As[0][skq+3][srow]=a4.w;
    Bs[0][skq+0][srow]=b4.x; Bs[0][skq+1][srow]=b4.y; Bs[0][skq+2][srow]=b4.z; Bs[0][skq+3][srow]=b4.w;
    __syncthreads();

    float acc[8][8];
#pragma unroll
    for (int r = 0; r < 8; r++)
#pragma unroll
        for (int c = 0; c < 8; c++) acc[r][c] = 0.f;

    for (int kt = 0; kt < 128; kt++) {
        int cur = kt & 1;
        float4 a4n, b4n;
        if (kt < 127) {
            a4n = *(const float4*)(ap + (size_t)(kt+1)*8);
            b4n = *(const float4*)(bp + (size_t)(kt+1)*8);
        }
#pragma unroll
        for (int k = 0; k < 8; k++) {
            float4 a0 = *(const float4*)&As[cur][k][ty<<2];
            float4 a1 = *(const float4*)&As[cur][k][64+(ty<<2)];
            float4 b0 = *(const float4*)&Bs[cur][k][tx<<2];
            float4 b1 = *(const float4*)&Bs[cur][k][64+(tx<<2)];
            float ar[8] = {a0.x,a0.y,a0.z,a0.w,a1.x,a1.y,a1.z,a1.w};
            float br[8] = {b0.x,b0.y,b0.z,b0.w,b1.x,b1.y,b1.z,b1.w};
#pragma unroll
            for (int r = 0; r < 8; r++)
#pragma unroll
                for (int c = 0; c < 8; c++) acc[r][c] += ar[r]*br[c];
        }
        if (kt < 127) {
            int nb = cur ^ 1;
            __syncthreads();
            As[nb][skq+0][srow]=a4n.x; As[nb][skq+1][srow]=a4n.y; As[nb][skq+2][srow]=a4n.z; As[nb][skq+3][srow]=a4n.w;
            Bs[nb][skq+0][srow]=b4n.x; Bs[nb][skq+1][srow]=b4n.y; Bs[nb][skq+2][srow]=b4n.z; Bs[nb][skq+3][srow]=b4n.w;
            __syncthreads();
        }
    }
    float4 ba0 = *(const float4*)&bias[n0 + (tx<<2)];
    float4 ba1 = *(const float4*)&bias[n0 + 64 + (tx<<2)];
#pragma unroll
    for (int r = 0; r < 8; r++) {
        int m = m0 + ((r < 4) ? (ty<<2)+r : 64+(ty<<2)+r-4);
        float* o = g_pre + (size_t)m * Dd + n0;
        float4 v0 = make_float4(acc[r][0]+ba0.x, acc[r][1]+ba0.y, acc[r][2]+ba0.z, acc[r][3]+ba0.w);
        float4 v1 = make_float4(acc[r][4]+ba1.x, acc[r][5]+ba1.y, acc[r][6]+ba1.z, acc[r][7]+ba1.w);
        *(float4*)(o + (tx<<2)) = v0;
        *(float4*)(o + 64 + (tx<<2)) = v1;
    }
}

// ---- persistent: power iteration prologue + mma recurrence. 64 blocks x 256 ----
__global__ void __launch_bounds__(256) k_recur(const float* __restrict__ Wh,
                                               const float* __restrict__ lr,
                                               const float* __restrict__ u0,
                                               const float* __restrict__ z,
                                               float* __restrict__ outp,
                                               float* __restrict__ hall) {
    __shared__ float sred[8 * 256];
    __shared__ float s_u[16];
    int tid = threadIdx.x, w = tid >> 5, lane = tid & 31, blk = blockIdx.x;
    unsigned nbar = 0;

    // ===== power iteration (3 iters) =====
    float invu = 1.f, ssu = 0.f;
    for (int it = 0; it < 3; it++) {
        if (tid < 16) {
            float uu = (it == 0) ? u0[blk*16 + tid] : __ldcg(&g_uraw[blk*16 + tid]) * invu;
            s_u[tid] = uu;
        }
        __syncthreads();
        {
            float4 acc = make_float4(0.f, 0.f, 0.f, 0.f);
            const float* wp = Wh + (size_t)(blk*16) * Dd + tid*4;
#pragma unroll
            for (int r = 0; r < 16; r++) {
                float uu = s_u[r];
                float4 wv = *(const float4*)(wp + (size_t)r * Dd);
                acc.x += uu*wv.x; acc.y += uu*wv.y; acc.z += uu*wv.z; acc.w += uu*wv.w;
            }
            *(float4*)&g_part[blk][tid*4] = acc;
        }
        gbar(&nbar);
        {
            int c = blk*16 + (tid & 15);
            int p0 = tid >> 4;
            float v = 0.f;
#pragma unroll
            for (int q = 0; q < 4; q++) v += __ldcg(&g_part[p0 + q*16][c]);
            sred[p0 * 16 + (tid & 15)] = v;
            __syncthreads();
            if (tid < 16) {
                float s = 0.f;
#pragma unroll
                for (int p = 0; p < 16; p++) s += sred[p*16 + tid];
                g_vraw[blk*16 + tid] = s;
                float ss = s * s;
#pragma unroll
                for (int o = 8; o > 0; o >>= 1) ss += __shfl_xor_sync(0xffffu, ss, o);
                if (tid == 0) g_ss[blk] = ss;
            }
        }
        gbar(&nbar);
        float ssv = 0.f;
#pragma unroll
        for (int q = 0; q < NB; q++) ssv += __ldcg(&g_ss[q]);
        float invv = 1.f / (sqrtf(ssv) + 1e-8f);
        __syncthreads();
        {
            float* sv = sred;
            for (int q = tid; q < Dd; q += 256) sv[q] = __ldcg(&g_vraw[q]) * invv;
            __syncthreads();
            float ro[2];
#pragma unroll
            for (int rr = 0; rr < 2; rr++) {
                int row = blk*16 + w*2 + rr;
                const float4* wp = (const float4*)(Wh + (size_t)row * Dd);
                float acc = 0.f;
#pragma unroll
                for (int q = 0; q < 8; q++) {
                    float4 a = wp[q*32 + lane];
                    float4 b = *(const float4*)&sv[(q*32 + lane)*4];
                    acc += a.x*b.x + a.y*b.y + a.z*b.z + a.w*b.w;
                }
#pragma unroll
                for (int o = 16; o > 0; o >>= 1) acc += __shfl_xor_sync(0xffffffffu, acc, o);
                ro[rr] = acc;
                if (lane == 0) g_uraw[row] = acc;
            }
            __syncthreads();
            if (lane == 0) { sred[w*2] = ro[0]; sred[w*2+1] = ro[1]; }
            __syncthreads();
            if (tid < 16) {
                float x = sred[tid];
                float ss = x * x;
#pragma unroll
                for (int o = 8; o > 0; o >>= 1) ss += __shfl_xor_sync(0xffffu, ss, o);
                if (tid == 0) g_ssu[blk] = ss;
            }
        }
        gbar(&nbar);
        ssu = 0.f;
#pragma unroll
        for (int q = 0; q < NB; q++) ssu += __ldcg(&g_ssu[q]);
        invu = 1.f / (sqrtf(ssu) + 1e-8f);
        __syncthreads();
    }
    float sigma = ssu / (sqrtf(ssu) + 1e-8f);

    // ===== build W_h_eff fragments in registers =====
    int i0 = blk * 16;
    float scl[2];
#pragma unroll
    for (int nt = 0; nt < 2; nt++) {
        int d = i0 + nt*8 + (lane >> 2);
        float rad = 0.999f / (1.f + expf(-lr[d]));
        scl[nt] = rad / (sigma + 1e-8f);
    }
    unsigned WHI[8][2][2], WLO[8][2][2];
#pragma unroll
    for (int k8 = 0; k8 < 8; k8++)
#pragma unroll
        for (int nt = 0; nt < 2; nt++)
#pragma unroll
            for (int r = 0; r < 2; r++) {
                int d = i0 + nt*8 + (lane >> 2);
                int jb = (w*8 + k8)*16 + ((lane & 3) << 1) + r*8;
                float v0 = Wh[(size_t)d * Dd + jb]     * scl[nt];
                float v1 = Wh[(size_t)d * Dd + jb + 1] * scl[nt];
                __nv_bfloat162 hh = __floats2bfloat162_rn(v0, v1);
                float r0 = v0 - __bfloat162float(hh.x);
                float r1 = v1 - __bfloat162float(hh.y);
                __nv_bfloat162 ll = __floats2bfloat162_rn(r0, r1);
                WHI[k8][nt][r] = *(unsigned*)&hh;
                WLO[k8][nt][r] = *(unsigned*)&ll;
            }

    // ===== recurrence (flag-array barrier) =====
    int gb = tid >> 4, dl = tid & 15, gd = i0 + dl;
    for (int t = 0; t < Tt; t++) {
        size_t row = ((size_t)(t*Bb) + gb) * Dd + gd;
        float pre_v = __ldcs(&g_pre[row]);
        float z_v   = __ldcs(&z[row]);

        if (t > 0) {
            if (tid < NB) {
                const unsigned* fp = &g_flag[tid];
                unsigned f;
                do {
                    asm volatile("ld.acquire.gpu.global.u32 %0, [%1];" : "=r"(f) : "l"(fp) : "memory");
                } while (f < (unsigned)t);
            }
            __syncthreads();
        }

        const uint4* src = (const uint4*)g_hA[t & 1];
        float C0[4] = {0.f,0.f,0.f,0.f}, C1[4] = {0.f,0.f,0.f,0.f};
        uint4 bh[4], bl[4];
#pragma unroll
        for (int p = 0; p < 4; p++) {
            int kt = w*8 + p;
            bh[p] = __ldcg(src + (kt*32 + lane)*2);
            bl[p] = __ldcg(src + (kt*32 + lane)*2 + 1);
        }
#pragma unroll
        for (int k8 = 0; k8 < 8; k8++) {
            unsigned ah[4] = {bh[k8 & 3].x, bh[k8 & 3].y, bh[k8 & 3].z, bh[k8 & 3].w};
            unsigned al[4] = {bl[k8 & 3].x, bl[k8 & 3].y, bl[k8 & 3].z, bl[k8 & 3].w};
            if (k8 < 4) {
                int kt = w*8 + k8 + 4;
                bh[k8] = __ldcg(src + (kt*32 + lane)*2);
                bl[k8] = __ldcg(src + (kt*32 + lane)*2 + 1);
            }
            mma16816(C0, ah, WHI[k8][0]);
            mma16816(C0, al, WHI[k8][0]);
            mma16816(C0, ah, WLO[k8][0]);
            mma16816(C1, ah, WHI[k8][1]);
            mma16816(C1, al, WHI[k8][1]);
            mma16816(C1, ah, WLO[k8][1]);
        }
        {
            int r = lane >> 2, c2 = (lane & 3) << 1;
            float* dst = &sred[w * 256];
            dst[ r*16      + c2    ] = C0[0];
            dst[ r*16      + c2 + 1] = C0[1];
            dst[(r+8)*16   + c2    ] = C0[2];
            dst[(r+8)*16   + c2 + 1] = C0[3];
            dst[ r*16  + 8 + c2    ] = C1[0];
            dst[ r*16  + 8 + c2 + 1] = C1[1];
            dst[(r+8)*16+8 + c2    ] = C1[2];
            dst[(r+8)*16+8 + c2 + 1] = C1[3];
        }
        __syncthreads();
        float acc = pre_v;
#pragma unroll
        for (int ww = 0; ww < 8; ww++) acc += sred[ww*256 + tid];
        float h = tanhf(acc);
        float gate = z_v / (1.f + expf(-z_v));
        outp[row] = h * gate;
        hall[(size_t)(t+1) * BD + gb*Dd + gd] = h;
        __nv_bfloat16 hb = __float2bfloat16(h);
        float rem = h - __bfloat162float(hb);
        __nv_bfloat16 lb = __float2bfloat16(rem);
        int fi = frag_idx(gb, gd);
        __nv_bfloat16* df = &g_hA[(t+1) & 1][fi];
        df[0] = hb;
        df[8] = lb;
        __syncthreads();
        if (tid == 0) {
            __threadfence();
            asm volatile("st.release.gpu.global.u32 [%0], %1;" :: "l"(&g_flag[blk]), "r"((unsigned)(t+1)) : "memory");
        }
    }
}

extern "C" void kernel_launch(void* const* d_in, const int* in_sizes, int n_in,
                              void* d_out, int out_size) {
    const float* x  = (const float*)d_in[0];
    const float* z  = (const float*)d_in[1];
    const float* h0 = (const float*)d_in[2];
    const float* Wx = (const float*)d_in[3];
    const float* Wh = (const float*)d_in[4];
    const float* lr = (const float*)d_in[5];
    const float* b  = (const float*)d_in[6];
    const float* u0 = (const float*)d_in[7];
    float* outp = (float*)d_out;
    float* hall = (float*)d_out + OUT_OFS;

    k_init<<<64, 256>>>(h0, hall);
    dim3 gg(Dd / 128, (Tt * Bb) / 128);
    k_gemm<<<gg, 256>>>(x, Wx, b);
    k_recur<<<NB, 256>>>(Wh, lr, u0, z, outp, hall);
}

// round 7
// speedup vs baseline: 5.7536x; 2.0178x over previous
#include <cuda_runtime.h>
#include <cuda_bf16.h>
#include <math.h>

#define Tt 1024
#define Bb 16
#define Dd 1024
#define NB 64
#define NGB 84
#define NTOT 148
#define BD (Bb*Dd)
#define OUT_OFS (Tt*Bb*Dd)

__device__ __align__(16) float g_pre[Tt*Bb*Dd];
__device__ __align__(16) __nv_bfloat16 g_hA[2][64*32*16]; // [phase][(kt*32+lt)*16 + rg*2+c]: 8 hi | 8 lo
__device__ __align__(16) float g_part[NB][Dd];
__device__ __align__(16) float g_vraw[Dd];
__device__ __align__(16) float g_uraw[Dd];
__device__ float g_ss[NB], g_ssu[NB];
__device__ unsigned g_arrive;
__device__ unsigned g_mtflag[128];

__device__ __forceinline__ void mma16816(float* c, const unsigned* a, const unsigned* b) {
    asm volatile(
        "mma.sync.aligned.m16n8k16.row.col.f32.bf16.bf16.f32 "
        "{%0,%1,%2,%3},{%4,%5,%6,%7},{%8,%9},{%0,%1,%2,%3};\n"
        : "+f"(c[0]), "+f"(c[1]), "+f"(c[2]), "+f"(c[3])
        : "r"(a[0]), "r"(a[1]), "r"(a[2]), "r"(a[3]), "r"(b[0]), "r"(b[1]));
}

__device__ __forceinline__ void gbar(unsigned* nbar) {
    (*nbar)++;
    __syncthreads();
    if (threadIdx.x == 0) {
        __threadfence();
        atomicAdd(&g_arrive, 1u);
        unsigned tgt = (*nbar) * NB;
        while (*(volatile unsigned*)&g_arrive < tgt) { }
        __threadfence();
    }
    __syncthreads();
}

__device__ __forceinline__ int frag_idx(int b, int j) {
    int kt = j >> 4, c = j & 15;
    int lt = ((b & 7) << 2) | ((c >> 1) & 3);
    int rg = (b >> 3) | ((c >> 3) << 1);
    return (kt * 32 + lt) * 16 + rg * 2 + (c & 1);
}

// ---- init ----
__global__ void k_init(const float* __restrict__ h0, float* __restrict__ hall) {
    int e = blockIdx.x * 256 + threadIdx.x;
    if (e == 0) g_arrive = 0u;
    if (e < 128) g_mtflag[e] = 0u;
    int b = e >> 10, j = e & 1023;
    float v = h0[e];
    hall[e] = v;
    __nv_bfloat16 hb = __float2bfloat16(v);
    float rem = v - __bfloat162float(hb);
    __nv_bfloat16 lb = __float2bfloat16(rem);
    int fi = frag_idx(b, j);
    g_hA[0][fi] = hb;
    g_hA[0][fi + 8] = lb;
}

// ---- fused persistent kernel: blocks 0..63 recurrence, 64..147 GEMM tiles ----
__global__ void __launch_bounds__(256) k_main(const float* __restrict__ A,
                                              const float* __restrict__ Bw,
                                              const float* __restrict__ bias,
                                              const float* __restrict__ Wh,
                                              const float* __restrict__ lr,
                                              const float* __restrict__ u0,
                                              const float* __restrict__ z,
                                              float* __restrict__ outp,
                                              float* __restrict__ hall) {
    __shared__ float sred[8 * 256];
    __shared__ float s_u[16];
    __shared__ float As[2][8][132], Bs[2][8][132];
    int tid = threadIdx.x, w = tid >> 5, lane = tid & 31;

    if (blockIdx.x >= NB) {
        // ================= GEMM role: tiles i = mt*8+nt, strided over 84 blocks =================
        int bg = blockIdx.x - NB;
        int srow = tid >> 1, skq = (tid & 1) << 2;
        int tx = tid & 15, ty = tid >> 4;
        for (int i = bg; i < 1024; i += NGB) {
            int m0 = (i >> 3) << 7, n0 = (i & 7) << 7;
            const float* ap = A  + (size_t)(m0 + srow) * Dd + skq;
            const float* bp = Bw + (size_t)(n0 + srow) * Dd + skq;

            float4 a4 = *(const float4*)ap;
            float4 b4 = *(const float4*)bp;
            As[0][skq+0][srow]=a4.x; As[0][skq+1][srow]=a4.y; As[0][skq+2][srow]=a4.z; As[0][skq+3][srow]=a4.w;
            Bs[0][skq+0][srow]=b4.x; Bs[0][skq+1][srow]=b4.y; Bs[0][skq+2][srow]=b4.z; Bs[0][skq+3][srow]=b4.w;
            __syncthreads();

            float acc[8][8];
#pragma unroll
            for (int r = 0; r < 8; r++)
#pragma unroll
                for (int c = 0; c < 8; c++) acc[r][c] = 0.f;

            for (int kt = 0; kt < 128; kt++) {
                int cur = kt & 1;
                float4 a4n, b4n;
                if (kt < 127) {
                    a4n = *(const float4*)(ap + (size_t)(kt+1)*8);
                    b4n = *(const float4*)(bp + (size_t)(kt+1)*8);
                }
#pragma unroll
                for (int k = 0; k < 8; k++) {
                    float4 a0 = *(const float4*)&As[cur][k][ty<<2];
                    float4 a1 = *(const float4*)&As[cur][k][64+(ty<<2)];
                    float4 b0 = *(const float4*)&Bs[cur][k][tx<<2];
                    float4 b1 = *(const float4*)&Bs[cur][k][64+(tx<<2)];
                    float ar[8] = {a0.x,a0.y,a0.z,a0.w,a1.x,a1.y,a1.z,a1.w};
                    float br[8] = {b0.x,b0.y,b0.z,b0.w,b1.x,b1.y,b1.z,b1.w};
#pragma unroll
                    for (int r = 0; r < 8; r++)
#pragma unroll
                        for (int c = 0; c < 8; c++) acc[r][c] += ar[r]*br[c];
                }
                if (kt < 127) {
                    int nb2 = cur ^ 1;
                    __syncthreads();
                    As[nb2][skq+0][srow]=a4n.x; As[nb2][skq+1][srow]=a4n.y; As[nb2][skq+2][srow]=a4n.z; As[nb2][skq+3][srow]=a4n.w;
                    Bs[nb2][skq+0][srow]=b4n.x; Bs[nb2][skq+1][srow]=b4n.y; Bs[nb2][skq+2][srow]=b4n.z; Bs[nb2][skq+3][srow]=b4n.w;
                    __syncthreads();
                }
            }
            float4 ba0 = *(const float4*)&bias[n0 + (tx<<2)];
            float4 ba1 = *(const float4*)&bias[n0 + 64 + (tx<<2)];
#pragma unroll
            for (int r = 0; r < 8; r++) {
                int m = m0 + ((r < 4) ? (ty<<2)+r : 64+(ty<<2)+r-4);
                float* o = g_pre + (size_t)m * Dd + n0;
                float4 v0 = make_float4(acc[r][0]+ba0.x, acc[r][1]+ba0.y, acc[r][2]+ba0.z, acc[r][3]+ba0.w);
                float4 v1 = make_float4(acc[r][4]+ba1.x, acc[r][5]+ba1.y, acc[r][6]+ba1.z, acc[r][7]+ba1.w);
                *(float4*)(o + (tx<<2)) = v0;
                *(float4*)(o + 64 + (tx<<2)) = v1;
            }
            __syncthreads();
            if (tid == 0) {
                __threadfence();
                atomicAdd(&g_mtflag[i >> 3], 1u);
            }
        }
        return;
    }

    // ================= recurrence role (blocks 0..63) =================
    int blk = blockIdx.x;
    unsigned nbar = 0;

    // ===== power iteration (3 iters) =====
    float invu = 1.f, ssu = 0.f;
    for (int it = 0; it < 3; it++) {
        if (tid < 16) {
            float uu = (it == 0) ? u0[blk*16 + tid] : __ldcg(&g_uraw[blk*16 + tid]) * invu;
            s_u[tid] = uu;
        }
        __syncthreads();
        {
            float4 acc = make_float4(0.f, 0.f, 0.f, 0.f);
            const float* wp = Wh + (size_t)(blk*16) * Dd + tid*4;
#pragma unroll
            for (int r = 0; r < 16; r++) {
                float uu = s_u[r];
                float4 wv = *(const float4*)(wp + (size_t)r * Dd);
                acc.x += uu*wv.x; acc.y += uu*wv.y; acc.z += uu*wv.z; acc.w += uu*wv.w;
            }
            *(float4*)&g_part[blk][tid*4] = acc;
        }
        gbar(&nbar);
        {
            int c = blk*16 + (tid & 15);
            int p0 = tid >> 4;
            float v = 0.f;
#pragma unroll
            for (int q = 0; q < 4; q++) v += __ldcg(&g_part[p0 + q*16][c]);
            sred[p0 * 16 + (tid & 15)] = v;
            __syncthreads();
            if (tid < 16) {
                float s = 0.f;
#pragma unroll
                for (int p = 0; p < 16; p++) s += sred[p*16 + tid];
                g_vraw[blk*16 + tid] = s;
                float ss = s * s;
#pragma unroll
                for (int o = 8; o > 0; o >>= 1) ss += __shfl_xor_sync(0xffffu, ss, o);
                if (tid == 0) g_ss[blk] = ss;
            }
        }
        gbar(&nbar);
        float ssv = 0.f;
#pragma unroll
        for (int q = 0; q < NB; q++) ssv += __ldcg(&g_ss[q]);
        float invv = 1.f / (sqrtf(ssv) + 1e-8f);
        __syncthreads();
        {
            float* sv = sred;
            for (int q = tid; q < Dd; q += 256) sv[q] = __ldcg(&g_vraw[q]) * invv;
            __syncthreads();
            float ro[2];
#pragma unroll
            for (int rr = 0; rr < 2; rr++) {
                int row = blk*16 + w*2 + rr;
                const float4* wp = (const float4*)(Wh + (size_t)row * Dd);
                float acc = 0.f;
#pragma unroll
                for (int q = 0; q < 8; q++) {
                    float4 a = wp[q*32 + lane];
                    float4 b = *(const float4*)&sv[(q*32 + lane)*4];
                    acc += a.x*b.x + a.y*b.y + a.z*b.z + a.w*b.w;
                }
#pragma unroll
                for (int o = 16; o > 0; o >>= 1) acc += __shfl_xor_sync(0xffffffffu, acc, o);
                ro[rr] = acc;
                if (lane == 0) g_uraw[row] = acc;
            }
            __syncthreads();
            if (lane == 0) { sred[w*2] = ro[0]; sred[w*2+1] = ro[1]; }
            __syncthreads();
            if (tid < 16) {
                float x = sred[tid];
                float ss = x * x;
#pragma unroll
                for (int o = 8; o > 0; o >>= 1) ss += __shfl_xor_sync(0xffffu, ss, o);
                if (tid == 0) g_ssu[blk] = ss;
            }
        }
        gbar(&nbar);
        ssu = 0.f;
#pragma unroll
        for (int q = 0; q < NB; q++) ssu += __ldcg(&g_ssu[q]);
        invu = 1.f / (sqrtf(ssu) + 1e-8f);
        __syncthreads();
    }
    float sigma = ssu / (sqrtf(ssu) + 1e-8f);

    // ===== build W_h_eff fragments in registers =====
    int i0 = blk * 16;
    float scl[2];
#pragma unroll
    for (int nt = 0; nt < 2; nt++) {
        int d = i0 + nt*8 + (lane >> 2);
        float rad = 0.999f / (1.f + expf(-lr[d]));
        scl[nt] = rad / (sigma + 1e-8f);
    }
    unsigned WHI[8][2][2], WLO[8][2][2];
#pragma unroll
    for (int k8 = 0; k8 < 8; k8++)
#pragma unroll
        for (int nt = 0; nt < 2; nt++)
#pragma unroll
            for (int r = 0; r < 2; r++) {
                int d = i0 + nt*8 + (lane >> 2);
                int jb = (w*8 + k8)*16 + ((lane & 3) << 1) + r*8;
                float v0 = Wh[(size_t)d * Dd + jb]     * scl[nt];
                float v1 = Wh[(size_t)d * Dd + jb + 1] * scl[nt];
                __nv_bfloat162 hh = __floats2bfloat162_rn(v0, v1);
                float r0 = v0 - __bfloat162float(hh.x);
                float r1 = v1 - __bfloat162float(hh.y);
                __nv_bfloat162 ll = __floats2bfloat162_rn(r0, r1);
                WHI[k8][nt][r] = *(unsigned*)&hh;
                WLO[k8][nt][r] = *(unsigned*)&ll;
            }

    // ===== recurrence =====
    int gb = tid >> 4, dl = tid & 15, gd = i0 + dl;
    for (int t = 0; t < Tt; t++) {
        if ((t & 7) == 0) {  // wait for this 8-step chunk of g_pre
            if (tid == 0) {
                const unsigned* fp = &g_mtflag[t >> 3];
                unsigned f;
                do {
                    asm volatile("ld.acquire.gpu.global.u32 %0, [%1];" : "=r"(f) : "l"(fp) : "memory");
                } while (f < 8u);
            }
            __syncthreads();
        }
        size_t row = ((size_t)(t*Bb) + gb) * Dd + gd;
        float pre_v = __ldcs(&g_pre[row]);
        float z_v   = __ldcs(&z[row]);

        const uint4* src = (const uint4*)g_hA[t & 1];
        float C0[4] = {0.f,0.f,0.f,0.f}, C1[4] = {0.f,0.f,0.f,0.f};
        uint4 bh[4], bl[4];
#pragma unroll
        for (int p = 0; p < 4; p++) {
            int kt = w*8 + p;
            bh[p] = __ldcg(src + (kt*32 + lane)*2);
            bl[p] = __ldcg(src + (kt*32 + lane)*2 + 1);
        }
#pragma unroll
        for (int k8 = 0; k8 < 8; k8++) {
            unsigned ah[4] = {bh[k8 & 3].x, bh[k8 & 3].y, bh[k8 & 3].z, bh[k8 & 3].w};
            unsigned al[4] = {bl[k8 & 3].x, bl[k8 & 3].y, bl[k8 & 3].z, bl[k8 & 3].w};
            if (k8 < 4) {
                int kt = w*8 + k8 + 4;
                bh[k8] = __ldcg(src + (kt*32 + lane)*2);
                bl[k8] = __ldcg(src + (kt*32 + lane)*2 + 1);
            }
            mma16816(C0, ah, WHI[k8][0]);
            mma16816(C0, al, WHI[k8][0]);
            mma16816(C0, ah, WLO[k8][0]);
            mma16816(C1, ah, WHI[k8][1]);
            mma16816(C1, al, WHI[k8][1]);
            mma16816(C1, ah, WLO[k8][1]);
        }
        {
            int r = lane >> 2, c2 = (lane & 3) << 1;
            float* dst = &sred[w * 256];
            dst[ r*16      + c2    ] = C0[0];
            dst[ r*16      + c2 + 1] = C0[1];
            dst[(r+8)*16   + c2    ] = C0[2];
            dst[(r+8)*16   + c2 + 1] = C0[3];
            dst[ r*16  + 8 + c2    ] = C1[0];
            dst[ r*16  + 8 + c2 + 1] = C1[1];
            dst[(r+8)*16+8 + c2    ] = C1[2];
            dst[(r+8)*16+8 + c2 + 1] = C1[3];
        }
        __syncthreads();
        float acc = pre_v;
#pragma unroll
        for (int ww = 0; ww < 8; ww++) acc += sred[ww*256 + tid];
        float h = tanhf(acc);
        float gate = z_v / (1.f + expf(-z_v));
        __nv_bfloat16 hb = __float2bfloat16(h);
        float rem = h - __bfloat162float(hb);
        __nv_bfloat16 lb = __float2bfloat16(rem);
        int fi = frag_idx(gb, gd);
        __nv_bfloat16* df = &g_hA[(t+1) & 1][fi];
        df[0] = hb;
        df[8] = lb;
        gbar(&nbar);
        // deferred (off the fence critical path)
        outp[row] = h * gate;
        hall[(size_t)(t+1) * BD + gb*Dd + gd] = h;
    }
}

extern "C" void kernel_launch(void* const* d_in, const int* in_sizes, int n_in,
                              void* d_out, int out_size) {
    const float* x  = (const float*)d_in[0];
    const float* z  = (const float*)d_in[1];
    const float* h0 = (const float*)d_in[2];
    const float* Wx = (const float*)d_in[3];
    const float* Wh = (const float*)d_in[4];
    const float* lr = (const float*)d_in[5];
    const float* b  = (const float*)d_in[6];
    const float* u0 = (const float*)d_in[7];
    float* outp = (float*)d_out;
    float* hall = (float*)d_out + OUT_OFS;

    k_init<<<64, 256>>>(h0, hall);
    k_main<<<NTOT, 256>>>(x, Wx, b, Wh, lr, u0, z, outp, hall);
}